// round 9
// baseline (speedup 1.0000x reference)
#include <cuda_runtime.h>

#define C16  16
#define GH32 32
#define W512 512
#define HW   (512 * 512)

// All weights on the constant bank. Evidence (R5 vs R7/R8 deltas) says these
// compile-time-offset loads go through the uniform LDCU port (floor 1), so
// const traffic is nearly free and smem can be eliminated entirely, keeping
// the full L1D carveout for the x gather.
#define OFF_W1 0        // [c][j]      16*32
#define OFF_W2 512      // [c][j]      16*32  (= g1w[:,16:] @ mw, folded)
#define OFF_G2 1024     // [gp][j][e]  8*32*2 (= g2w[2gp+e][j])
#define OFF_MW 1536     // [c][d]      16*16  (= mw[d][c])
#define OFF_B1 1792     // 32            (= g1b + g1w[:,16:] @ mb)
#define OFF_GB 1824     // 16            (g2b)
#define OFF_MB 1840     // 16            (mb)
#define NWC    1856

__constant__ __align__(16) float cwts[NWC];
__device__   __align__(16) float g_wbuf[NWC];

// Packed f32x2 FMA (Blackwell sm_103a) — 2 fp32 FMAs per instruction.
__device__ __forceinline__ float2 ffma2(float2 a, float2 b, float2 c) {
    float2 d;
    asm("fma.rn.f32x2 %0, %1, %2, %3;"
        : "=l"(reinterpret_cast<unsigned long long&>(d))
        : "l"(reinterpret_cast<unsigned long long&>(a)),
          "l"(reinterpret_cast<unsigned long long&>(b)),
          "l"(reinterpret_cast<unsigned long long&>(c)));
    return d;
}
__device__ __forceinline__ float2 dup2(float v) { return make_float2(v, v); }
__device__ __forceinline__ float4 ldc4(int idx) {
    return *reinterpret_cast<const float4*>(&cwts[idx]);
}
__device__ __forceinline__ float2 ldc2(int idx) {
    return *reinterpret_cast<const float2*>(&cwts[idx]);
}

// ---- prep: fold weights into constant staging buffer ----
__global__ void prep_weights(const float* __restrict__ mw,  const float* __restrict__ mb,
                             const float* __restrict__ g1w, const float* __restrict__ g1b,
                             const float* __restrict__ g2w, const float* __restrict__ g2b)
{
    const int t = threadIdx.x;
    for (int i = t; i < C16 * GH32; i += 256) {
        int c = i >> 5, j = i & 31;
        g_wbuf[OFF_W1 + i] = g1w[j * (2 * C16) + c];
        float acc = 0.f;
        #pragma unroll
        for (int k = 0; k < C16; k++)
            acc += g1w[j * (2 * C16) + C16 + k] * mw[k * C16 + c];
        g_wbuf[OFF_W2 + i] = acc;
    }
    for (int i = t; i < 8 * GH32 * 2; i += 256) {
        int gp = i >> 6, r = i & 63, j = r >> 1, e = r & 1;
        g_wbuf[OFF_G2 + i] = g2w[(2 * gp + e) * GH32 + j];
    }
    if (t < 256) {
        int c = t >> 4, d = t & 15;
        g_wbuf[OFF_MW + t] = mw[d * C16 + c];
    }
    if (t < GH32) {
        float acc = g1b[t];
        #pragma unroll
        for (int k = 0; k < C16; k++)
            acc += g1w[t * (2 * C16) + C16 + k] * mb[k];
        g_wbuf[OFF_B1 + t] = acc;
    }
    if (t >= 32 && t < 32 + C16) g_wbuf[OFF_MB + t - 32] = mb[t - 32];
    if (t >= 64 && t < 64 + C16) g_wbuf[OFF_GB + t - 64] = g2b[t - 64];
}

// Identity: softmax over 8 identical affinities = 1/8 each, so
//   s      = mean of 8 rolls of x
//   agg    = mw @ s + mb
//   hidden = relu(W1 @ x + W2 @ s + b1')
//   out    = agg * sigmoid(g2w @ hidden + g2b)
//
// ONE pixel per thread, f32x2 packed along OUTPUT channels (FFMA2 density
// unchanged: 896 FFMA2/px). ~70 live regs -> __launch_bounds__(256,3) gives
// 24 warps/SM with ZERO smem (full L1D carveout preserved — the R6 lesson).
// Lanes map to adjacent pixels: every gather/center/store access coalesces.
__global__ __launch_bounds__(256, 3) void fused_graphaug_kernel(
    const float* __restrict__ x,
    float* __restrict__ out)
{
    const int t = threadIdx.x;
    const int p = blockIdx.x * 256 + t;          // pixel index
    const int w = p & (W512 - 1);
    const int h = (p >> 9) & (W512 - 1);
    const int b = p >> 18;

    const float* xb    = x + (size_t)b * C16 * HW;
    const int    center = h * W512 + w;

    // Fixed offsets (dy,dx); source = ((h-dy)&511, (w-dx)&511)
    constexpr int DY[8] = {-4, -4, -4, -3, -2, 2, 3, 4};
    constexpr int DX[8] = {-4, -1,  2,  4, -3, 3, -2, 4};
    int poff[8];
    #pragma unroll
    for (int i = 0; i < 8; i++)
        poff[i] = ((h - DY[i]) & (W512 - 1)) * W512 + ((w - DX[i]) & (W512 - 1));

    // ---- s = mean of 8 rolls per channel (coalesced scalar LDG) ----
    float sv[C16];
    #pragma unroll
    for (int c = 0; c < C16; c++) {
        const float* xp = xb + c * HW;
        float a01 = __ldg(xp + poff[0]) + __ldg(xp + poff[1]);
        float a23 = __ldg(xp + poff[2]) + __ldg(xp + poff[3]);
        float a45 = __ldg(xp + poff[4]) + __ldg(xp + poff[5]);
        float a67 = __ldg(xp + poff[6]) + __ldg(xp + poff[7]);
        sv[c] = (a01 + a23 + a45 + a67) * 0.125f;
    }

    // ---- gate accumulators: gacc[gp] packs outputs (2gp, 2gp+1) ----
    float2 gacc[8];
    #pragma unroll
    for (int gp = 0; gp < 8; gp++)
        gacc[gp] = ldc2(OFF_GB + 2 * gp);

    // ---- hidden in 2 chunks of 16 units (8 j-pairs each) ----
    #pragma unroll
    for (int jt = 0; jt < 2; jt++) {
        const int j0 = jt * 16;
        float2 hreg[8];                          // pairs (j0+2l, j0+2l+1)
        #pragma unroll
        for (int jl = 0; jl < 8; jl++)
            hreg[jl] = ldc2(OFF_B1 + j0 + 2 * jl);

        // W1 @ x (center x reload per chunk: coalesced, L1-resident)
        #pragma unroll
        for (int c = 0; c < C16; c++) {
            float2 xd = dup2(__ldg(xb + c * HW + center));
            #pragma unroll
            for (int q = 0; q < 4; q++) {
                float4 wq = ldc4(OFF_W1 + c * GH32 + j0 + 4 * q);
                hreg[2*q]   = ffma2(make_float2(wq.x, wq.y), xd, hreg[2*q]);
                hreg[2*q+1] = ffma2(make_float2(wq.z, wq.w), xd, hreg[2*q+1]);
            }
        }
        // W2 @ s
        #pragma unroll
        for (int c = 0; c < C16; c++) {
            float2 sd = dup2(sv[c]);
            #pragma unroll
            for (int q = 0; q < 4; q++) {
                float4 wq = ldc4(OFF_W2 + c * GH32 + j0 + 4 * q);
                hreg[2*q]   = ffma2(make_float2(wq.x, wq.y), sd, hreg[2*q]);
                hreg[2*q+1] = ffma2(make_float2(wq.z, wq.w), sd, hreg[2*q+1]);
            }
        }
        // relu
        #pragma unroll
        for (int jl = 0; jl < 8; jl++) {
            hreg[jl].x = fmaxf(hreg[jl].x, 0.f);
            hreg[jl].y = fmaxf(hreg[jl].y, 0.f);
        }
        // gate accumulation
        #pragma unroll
        for (int jl = 0; jl < 8; jl++) {
            const int jg = j0 + 2 * jl;
            float2 ha = dup2(hreg[jl].x), hb = dup2(hreg[jl].y);
            #pragma unroll
            for (int gp = 0; gp < 8; gp++) {
                float4 wq = ldc4(OFF_G2 + gp * 64 + jg * 2);
                gacc[gp] = ffma2(make_float2(wq.x, wq.y), ha, gacc[gp]);
                gacc[gp] = ffma2(make_float2(wq.z, wq.w), hb, gacc[gp]);
            }
        }
    }

    // ---- agg = mw @ s + mb : agg[dp] packs outputs (2dp, 2dp+1) ----
    float2 agg[8];
    #pragma unroll
    for (int dp = 0; dp < 8; dp++)
        agg[dp] = ldc2(OFF_MB + 2 * dp);
    #pragma unroll
    for (int c = 0; c < C16; c++) {
        float2 sd = dup2(sv[c]);
        #pragma unroll
        for (int q = 0; q < 4; q++) {
            float4 wq = ldc4(OFF_MW + c * C16 + 4 * q);
            agg[2*q]   = ffma2(make_float2(wq.x, wq.y), sd, agg[2*q]);
            agg[2*q+1] = ffma2(make_float2(wq.z, wq.w), sd, agg[2*q+1]);
        }
    }

    // ---- epilogue: out = agg * sigmoid(gacc) (coalesced scalar stores) ----
    float* ob = out + (size_t)b * C16 * HW + center;
    #pragma unroll
    for (int dp = 0; dp < 8; dp++) {
        float g0 = 1.f / (1.f + __expf(-gacc[dp].x));
        float g1 = 1.f / (1.f + __expf(-gacc[dp].y));
        ob[(size_t)(2 * dp)     * HW] = agg[dp].x * g0;
        ob[(size_t)(2 * dp + 1) * HW] = agg[dp].y * g1;
    }
}

extern "C" void kernel_launch(void* const* d_in, const int* in_sizes, int n_in,
                              void* d_out, int out_size) {
    // metadata order: x, qw, qb, kw, kb, mw, mb, scaling, g1w, g1b, g2w, g2b
    const float* x   = (const float*)d_in[0];
    const float* mw  = (const float*)d_in[5];
    const float* mb  = (const float*)d_in[6];
    const float* g1w = (const float*)d_in[8];
    const float* g1b = (const float*)d_in[9];
    const float* g2w = (const float*)d_in[10];
    const float* g2b = (const float*)d_in[11];
    float* out = (float*)d_out;

    prep_weights<<<1, 256>>>(mw, mb, g1w, g1b, g2w, g2b);

    void* wsrc = nullptr;
    cudaGetSymbolAddress(&wsrc, g_wbuf);
    cudaMemcpyToSymbolAsync(cwts, wsrc, NWC * sizeof(float), 0,
                            cudaMemcpyDeviceToDevice, 0);

    // 1,048,576 pixels -> 4096 blocks x 256 threads (1 px/thread)
    fused_graphaug_kernel<<<4096, 256>>>(x, out);
}